// round 7
// baseline (speedup 1.0000x reference)
#include <cuda_runtime.h>

// Problem constants (from reference)
#define B        4096
#define N_ELEM   2048
#define N_NODES  1024
#define E2       4096
#define G        2                     // batches per group
#define NGROUPS  (B / G)               // 2048 groups
#define NBLK     152                   // 1 CTA/SM, persistent
#define THREADS  1024                  // 1 node per thread

// __device__ scratch (16B-aligned for cp.async.bulk sources).
__device__ __align__(16) int    g_elem[E2];
__device__ __align__(16) float2 g_vec[E2];
__device__ __align__(16) int    g_off[N_NODES + 4];
__device__ __align__(16) int    g_nid[N_NODES];      // degree-sorted node perm
__device__ float g_part[NBLK];
__device__ int   g_ctr = 0;

// Dynamic smem layout (bytes):
#define OFF_ELEM   0                    // int[E2]        16K
#define OFF_VEC    (16 * 1024)          // float2[E2]     32K
#define OFF_OFF    (48 * 1024)          // int[N_NODES+4] ~4K
#define OFF_NID    (53 * 1024)          // int[N_NODES]    4K
#define OFF_AXIAL  (60 * 1024)          // float2[N_ELEM] 16K
#define OFF_BUF0   (80 * 1024)          // 64K: [EA|e|q|r]
#define OFF_BUF1   (144 * 1024)         // 64K
#define SMEM_BYTES (208 * 1024)

#define CSR_BYTES   (16384 + 32768 + 4112 + 4096)
#define GRP_BYTES   (4 * 16384)

__device__ __forceinline__ unsigned smem_u32(const void* p) {
    return (unsigned)__cvta_generic_to_shared(p);
}
__device__ __forceinline__ void mbar_init(unsigned mbar, unsigned count) {
    asm volatile("mbarrier.init.shared.b64 [%0], %1;" :: "r"(mbar), "r"(count) : "memory");
}
__device__ __forceinline__ void mbar_expect_tx(unsigned mbar, unsigned bytes) {
    asm volatile("mbarrier.arrive.expect_tx.shared.b64 _, [%0], %1;"
                 :: "r"(mbar), "r"(bytes) : "memory");
}
__device__ __forceinline__ void mbar_wait(unsigned mbar, unsigned parity) {
    asm volatile(
        "{\n\t.reg .pred P;\n\t"
        "W%=:\n\t"
        "mbarrier.try_wait.parity.acquire.cta.shared::cta.b64 P, [%0], %1, 0x989680;\n\t"
        "@!P bra W%=;\n\t}"
        :: "r"(mbar), "r"(parity) : "memory");
}
__device__ __forceinline__ void bulk_g2s(unsigned dst_smem, const void* src,
                                         unsigned bytes, unsigned mbar) {
    asm volatile(
        "cp.async.bulk.shared::cta.global.mbarrier::complete_tx::bytes [%0], [%1], %2, [%3];"
        :: "r"(dst_smem), "l"(src), "r"(bytes), "r"(mbar) : "memory");
}

// ---------------------------------------------------------------------------
// Setup: deterministic CSR + degree-sorted node permutation. One block.
// ---------------------------------------------------------------------------
__global__ __launch_bounds__(N_NODES)
void nel_setup_kernel(const int* __restrict__ node_ids,
                      const int* __restrict__ elem_ids,
                      const float* __restrict__ vecs) {
    __shared__ int s_beg[N_NODES];
    __shared__ int s_cur[N_NODES];
    __shared__ int s_deg[N_NODES];
    __shared__ int s_idx[E2];
    __shared__ int s_wsum[32];
    __shared__ int s_dhist[64];
    __shared__ int s_dbase[64];
    const int tid  = threadIdx.x;
    const int lane = tid & 31;
    const int wrp  = tid >> 5;

    // 1. histogram
    s_beg[tid] = 0;
    if (tid < 64) s_dhist[tid] = 0;
    __syncthreads();
    #pragma unroll
    for (int i = tid; i < E2; i += N_NODES)
        atomicAdd(&s_beg[node_ids[i]], 1);
    __syncthreads();

    // 2. exclusive scan via warp shuffles
    const int cnt = s_beg[tid];
    int v = cnt;
    #pragma unroll
    for (int o = 1; o < 32; o <<= 1) {
        int t = __shfl_up_sync(0xffffffffu, v, o);
        if (lane >= o) v += t;
    }
    if (lane == 31) s_wsum[wrp] = v;
    __syncthreads();
    if (wrp == 0) {
        int w = s_wsum[lane];
        #pragma unroll
        for (int o = 1; o < 32; o <<= 1) {
            int t = __shfl_up_sync(0xffffffffu, w, o);
            if (lane >= o) w += t;
        }
        s_wsum[lane] = w - s_wsum[lane];
    }
    __syncthreads();
    const int excl = v - cnt + s_wsum[wrp];
    s_beg[tid] = excl;
    s_cur[tid] = excl;
    s_deg[tid] = (cnt < 63) ? cnt : 63;
    atomicAdd(&s_dhist[(cnt < 63) ? cnt : 63], 1);
    __syncthreads();

    // 3. scatter edge indices into bins
    #pragma unroll
    for (int i = tid; i < E2; i += N_NODES) {
        int pos = atomicAdd(&s_cur[node_ids[i]], 1);
        s_idx[pos] = i;
    }
    __syncthreads();

    // 4. per-bin insertion sort -> deterministic edge order
    {
        const int beg = s_beg[tid], end = s_cur[tid];
        for (int a = beg + 1; a < end; a++) {
            int key = s_idx[a];
            int p = a - 1;
            while (p >= beg && s_idx[p] > key) { s_idx[p + 1] = s_idx[p]; p--; }
            s_idx[p + 1] = key;
        }
    }

    // 4b. degree-descending node permutation (deterministic: id asc per bucket)
    if (tid == 0) {
        int running = 0;
        for (int d = 63; d >= 0; d--) { s_dbase[d] = running; running += s_dhist[d]; }
    }
    __syncthreads();
    if (tid < 64) {
        int pos = s_dbase[tid];
        for (int id = 0; id < N_NODES; id++)
            if (s_deg[id] == tid) g_nid[pos++] = id;
    }

    // 5. write split CSR arrays
    g_off[tid] = s_beg[tid];
    if (tid == 0) {
        g_off[N_NODES] = E2; g_off[N_NODES + 1] = E2;
        g_off[N_NODES + 2] = E2; g_off[N_NODES + 3] = E2;
    }
    __syncthreads();
    #pragma unroll
    for (int i = tid; i < E2; i += N_NODES) {
        int idx = s_idx[i];
        g_elem[i] = elem_ids[idx];
        g_vec[i]  = make_float2(vecs[2 * idx], vecs[2 * idx + 1]);
    }
}

// ---------------------------------------------------------------------------
// Main: 152 persistent blocks, 1024 threads. TMA bulk copies for all streams,
// double-buffered. Thread t handles degree-sorted node nid[t] -> near-zero
// warp divergence in the gather.
// ---------------------------------------------------------------------------
__global__ __launch_bounds__(THREADS, 1)
void nel_main_kernel(const float* __restrict__ EA,
                     const float* __restrict__ e,
                     const float* __restrict__ q,
                     const float* __restrict__ r,
                     float* __restrict__ out) {
    extern __shared__ unsigned char dyn[];
    int*    s_elem  = (int*)   (dyn + OFF_ELEM);
    float2* s_vec   = (float2*)(dyn + OFF_VEC);
    int*    s_off   = (int*)   (dyn + OFF_OFF);
    int*    s_nid   = (int*)   (dyn + OFF_NID);
    float2* s_axial = (float2*)(dyn + OFF_AXIAL);
    float*  s_buf0  = (float*) (dyn + OFF_BUF0);
    float*  s_buf1  = (float*) (dyn + OFF_BUF1);
    __shared__ __align__(8) unsigned long long s_mbar[2];
    __shared__ float s_warp[THREADS / 32];
    __shared__ int   s_islast;

    const int tid = threadIdx.x;
    const int g0  = blockIdx.x;
    const int cnt = (NGROUPS - g0 + NBLK - 1) / NBLK;
    const unsigned mb0 = smem_u32(&s_mbar[0]);
    const unsigned mb1 = smem_u32(&s_mbar[1]);

    if (tid == 0) { mbar_init(mb0, 1); mbar_init(mb1, 1); }
    __syncthreads();

    // --- prologue: CSR + group 0 on mb0, group 1 on mb1 ---
    if (tid == 0) {
        {
            int grp = g0;
            mbar_expect_tx(mb0, CSR_BYTES + GRP_BYTES);
            bulk_g2s(smem_u32(s_elem), g_elem, 16384, mb0);
            bulk_g2s(smem_u32(s_vec),  g_vec,  32768, mb0);
            bulk_g2s(smem_u32(s_off),  g_off,  4112,  mb0);
            bulk_g2s(smem_u32(s_nid),  g_nid,  4096,  mb0);
            bulk_g2s(smem_u32(s_buf0),         EA + (size_t)grp * G * N_ELEM,     16384, mb0);
            bulk_g2s(smem_u32(s_buf0 + 4096),  e  + (size_t)grp * G * N_ELEM,     16384, mb0);
            bulk_g2s(smem_u32(s_buf0 + 8192),  q  + (size_t)grp * G * N_NODES * 2, 16384, mb0);
            bulk_g2s(smem_u32(s_buf0 + 12288), r  + (size_t)grp * G * N_NODES * 2, 16384, mb0);
        }
        if (cnt > 1) {
            int grp = g0 + NBLK;
            mbar_expect_tx(mb1, GRP_BYTES);
            bulk_g2s(smem_u32(s_buf1),         EA + (size_t)grp * G * N_ELEM,     16384, mb1);
            bulk_g2s(smem_u32(s_buf1 + 4096),  e  + (size_t)grp * G * N_ELEM,     16384, mb1);
            bulk_g2s(smem_u32(s_buf1 + 8192),  q  + (size_t)grp * G * N_NODES * 2, 16384, mb1);
            bulk_g2s(smem_u32(s_buf1 + 12288), r  + (size_t)grp * G * N_NODES * 2, 16384, mb1);
        }
    }

    float acc = 0.f;
    unsigned ph0 = 0, ph1 = 0;
    int my_n = -1, my_beg = 0, my_end = 0;

    for (int k = 0; k < cnt; k++) {
        const int bsel = k & 1;
        float* buf = bsel ? s_buf1 : s_buf0;
        const unsigned mb = bsel ? mb1 : mb0;

        if (bsel) { mbar_wait(mb, ph1); ph1 ^= 1; }
        else      { mbar_wait(mb, ph0); ph0 ^= 1; }

        if (k == 0) {                       // CSR just arrived: cache node info
            my_n   = s_nid[tid];
            my_beg = s_off[my_n];
            my_end = s_off[my_n + 1];
        }

        // --- build axial[elem] = {EA_b0*e_b0, EA_b1*e_b1} ---
        #pragma unroll
        for (int i = tid; i < N_ELEM; i += THREADS) {
            float a0 = buf[i]          * buf[4096 + i];
            float a1 = buf[N_ELEM + i] * buf[4096 + N_ELEM + i];
            s_axial[i] = make_float2(a0, a1);
        }
        __syncthreads();

        // --- gather + loss for this thread's node, both batches ---
        const float2* sq = (const float2*)(buf + 8192);
        const float2* sr = (const float2*)(buf + 12288);
        {
            float ax0 = 0.f, ay0 = 0.f, ax1 = 0.f, ay1 = 0.f;
            for (int p = my_beg; p < my_end; p++) {
                int    eid = s_elem[p];
                float2 v   = s_vec[p];
                float2 a   = s_axial[eid];
                ax0 += a.x * v.x;  ay0 += a.x * v.y;
                ax1 += a.y * v.x;  ay1 += a.y * v.y;
            }
            float2 qq0 = sq[my_n];            float2 rr0 = sr[my_n];
            float2 qq1 = sq[N_NODES + my_n];  float2 rr1 = sr[N_NODES + my_n];
            float dx0 = ax0 - qq0.x - rr0.x, dy0 = ay0 - qq0.y - rr0.y;
            float dx1 = ax1 - qq1.x - rr1.x, dy1 = ay1 - qq1.y - rr1.y;
            acc += dx0 * dx0 + dy0 * dy0 + dx1 * dx1 + dy1 * dy1;
        }
        __syncthreads();   // everyone done reading buf before refill

        // --- prefetch group k+2 into this buffer ---
        if (tid == 0 && k + 2 < cnt) {
            int grp = g0 + (k + 2) * NBLK;
            mbar_expect_tx(mb, GRP_BYTES);
            bulk_g2s(smem_u32(buf),         EA + (size_t)grp * G * N_ELEM,     16384, mb);
            bulk_g2s(smem_u32(buf + 4096),  e  + (size_t)grp * G * N_ELEM,     16384, mb);
            bulk_g2s(smem_u32(buf + 8192),  q  + (size_t)grp * G * N_NODES * 2, 16384, mb);
            bulk_g2s(smem_u32(buf + 12288), r  + (size_t)grp * G * N_NODES * 2, 16384, mb);
        }
    }

    // --- block reduce ---
    #pragma unroll
    for (int o = 16; o > 0; o >>= 1)
        acc += __shfl_down_sync(0xffffffffu, acc, o);
    if ((tid & 31) == 0) s_warp[tid >> 5] = acc;
    __syncthreads();
    if (tid == 0) {
        float total = 0.f;
        #pragma unroll
        for (int w = 0; w < THREADS / 32; w++) total += s_warp[w];
        g_part[blockIdx.x] = total;
    }

    // --- last-block finalize (fixed-order double sum -> deterministic) ---
    __threadfence();
    if (tid == 0) {
        int old = atomicAdd(&g_ctr, 1);
        s_islast = (old == (int)gridDim.x - 1) ? 1 : 0;
    }
    __syncthreads();
    if (s_islast) {
        __threadfence();
        __shared__ double s_d[THREADS];
        double d = 0.0;
        #pragma unroll
        for (int i = tid; i < NBLK; i += THREADS) d += (double)g_part[i];
        s_d[tid] = d;
        __syncthreads();
        #pragma unroll
        for (int s = THREADS / 2; s > 0; s >>= 1) {
            if (tid < s) s_d[tid] += s_d[tid + s];
            __syncthreads();
        }
        if (tid == 0) {
            out[0] = (float)(s_d[0] / ((double)B * (double)N_NODES * 2.0));
            g_ctr = 0;   // reset for next graph replay
        }
    }
}

extern "C" void kernel_launch(void* const* d_in, const int* in_sizes, int n_in,
                              void* d_out, int out_size) {
    const float* EA       = (const float*)d_in[0];
    const float* e        = (const float*)d_in[1];
    const float* q        = (const float*)d_in[2];
    const float* r        = (const float*)d_in[3];
    const float* vecs     = (const float*)d_in[4];
    const int*   node_ids = (const int*)d_in[5];
    const int*   elem_ids = (const int*)d_in[6];
    float* out = (float*)d_out;

    static int configured = 0;
    if (!configured) {
        cudaFuncSetAttribute(nel_main_kernel,
                             cudaFuncAttributeMaxDynamicSharedMemorySize,
                             SMEM_BYTES);
        configured = 1;
    }

    nel_setup_kernel<<<1, N_NODES>>>(node_ids, elem_ids, vecs);
    nel_main_kernel<<<NBLK, THREADS, SMEM_BYTES>>>(EA, e, q, r, out);
}